// round 1
// baseline (speedup 1.0000x reference)
#include <cuda_runtime.h>
#include <math.h>
#include <math_constants.h>

#define Uu    128
#define Nn    512
#define Ff    80
#define FUF   64
#define TOPK  10
#define SLOTS 256      // slots 0..127 = ndcg scores, 128..255 = div scores
#define EPSV  1e-10f

// M0: initial softmax matrices for both score sets. p = diag(r) * M0 * diag(c).
static __device__ float g_M0[(size_t)SLOTS * Nn * Nn];   // 256 MB scratch
static __device__ float g_r[SLOTS * Nn];
static __device__ float g_c[SLOTS * Nn];

// ---------------------------------------------------------------------------
// init: per slot, compute a_sum, row-softmax of (v_i*s_j - A_j)*10, store M0,
// and fold in Sinkhorn column pass #1 (r == 1).
// ---------------------------------------------------------------------------
__global__ void __launch_bounds__(512) init_kernel(const float* __restrict__ s_ndcg,
                                                   const float* __restrict__ s_div) {
    int slot = blockIdx.x;
    const float* sp = (slot < Uu) ? (s_ndcg + (size_t)slot * Nn)
                                  : (s_div + (size_t)(slot - Uu) * Nn);
    __shared__ float sh_s[Nn];
    __shared__ float sh_A[Nn];
    __shared__ float sh_col[Nn];
    int tid = threadIdx.x;
    sh_s[tid]   = sp[tid];
    sh_col[tid] = 0.f;
    __syncthreads();
    {
        float sj = sh_s[tid];
        float a = 0.f;
        for (int k = 0; k < Nn; k++) a += fabsf(sj - sh_s[k]);
        sh_A[tid] = a;
        g_r[slot * Nn + tid] = 1.0f;
    }
    __syncthreads();

    int w = tid >> 5, lane = tid & 31;
    float colacc[16];
#pragma unroll
    for (int k = 0; k < 16; k++) colacc[k] = 0.f;
    float* base = g_M0 + (size_t)slot * Nn * Nn;

    for (int ii = 0; ii < 32; ii++) {           // warp w owns rows [32w, 32w+32)
        int i = (w << 5) + ii;
        float v = (float)(Nn - 1 - 2 * i);
        float x[16];
        float mx = -CUDART_INF_F;
#pragma unroll
        for (int k = 0; k < 16; k++) {
            int j = (k << 5) + lane;
            // match reference op order: mul, sub, then /tau (no FMA contraction)
            float l = __fsub_rn(__fmul_rn(v, sh_s[j]), sh_A[j]);
            x[k] = __fmul_rn(l, 10.0f);
            mx = fmaxf(mx, x[k]);
        }
#pragma unroll
        for (int o = 16; o > 0; o >>= 1) mx = fmaxf(mx, __shfl_xor_sync(0xffffffffu, mx, o));
        float sum = 0.f;
#pragma unroll
        for (int k = 0; k < 16; k++) {
            float t = x[k] - mx;
            // t < -105 underflows to exact 0 in fp32 (even subnormals) — skip expf
            float e = (t < -105.0f) ? 0.f : expf(t);
            x[k] = e;
            sum += e;
        }
#pragma unroll
        for (int o = 16; o > 0; o >>= 1) sum += __shfl_xor_sync(0xffffffffu, sum, o);
        float inv = 1.0f / sum;   // sum >= 1 (row max contributes exp(0)=1)
        float* row = base + (size_t)i * Nn;
#pragma unroll
        for (int k = 0; k < 16; k++) {
            float p = x[k] * inv;
            row[(k << 5) + lane] = p;
            colacc[k] += p;
        }
    }
#pragma unroll
    for (int k = 0; k < 16; k++) atomicAdd(&sh_col[(k << 5) + lane], colacc[k]);
    __syncthreads();
    // column update with c_old = 1:  c_new = 1 / max(colsum, EPS); zero-guard
    float acc = sh_col[tid];
    float c = (acc == 0.f) ? 0.f : (1.0f / fmaxf(acc, EPSV));
    g_c[slot * Nn + tid] = c;
}

// ---------------------------------------------------------------------------
// Sinkhorn row pass: rowsum_i = r_i * sum_j c_j M0[i,j]; r_i /= max(rowsum,EPS)
// ---------------------------------------------------------------------------
__global__ void __launch_bounds__(512) row_kernel() {
    int slot = blockIdx.x;
    __shared__ float sh_c[Nn];
    int tid = threadIdx.x;
    sh_c[tid] = g_c[slot * Nn + tid];
    __syncthreads();
    int w = tid >> 5, lane = tid & 31;
    const float* base = g_M0 + (size_t)slot * Nn * Nn;
    for (int ii = 0; ii < 32; ii++) {
        int i = (w << 5) + ii;
        const float* row = base + (size_t)i * Nn;
        float acc = 0.f;
#pragma unroll
        for (int k = 0; k < 16; k++) {
            int j = (k << 5) + lane;
            acc = fmaf(sh_c[j], row[j], acc);
        }
#pragma unroll
        for (int o = 16; o > 0; o >>= 1) acc += __shfl_xor_sync(0xffffffffu, acc, o);
        if (lane == 0) {
            float r = g_r[slot * Nn + i];
            float rn = (acc == 0.f) ? 0.f : r / fmaxf(r * acc, EPSV);
            g_r[slot * Nn + i] = rn;
        }
    }
}

// ---------------------------------------------------------------------------
// Sinkhorn col pass: colsum_j = c_j * sum_i r_i M0[i,j]; c_j /= max(colsum,EPS)
// ---------------------------------------------------------------------------
__global__ void __launch_bounds__(512) col_kernel() {
    int slot = blockIdx.x;
    __shared__ float sh_r[Nn];
    int tid = threadIdx.x;
    sh_r[tid] = g_r[slot * Nn + tid];
    __syncthreads();
    const float* cb = g_M0 + (size_t)slot * Nn * Nn + tid;
    float a0 = 0.f, a1 = 0.f, a2 = 0.f, a3 = 0.f;
#pragma unroll 4
    for (int i = 0; i < Nn; i += 4) {
        a0 = fmaf(sh_r[i    ], cb[(size_t)(i    ) * Nn], a0);
        a1 = fmaf(sh_r[i + 1], cb[(size_t)(i + 1) * Nn], a1);
        a2 = fmaf(sh_r[i + 2], cb[(size_t)(i + 2) * Nn], a2);
        a3 = fmaf(sh_r[i + 3], cb[(size_t)(i + 3) * Nn], a3);
    }
    float acc = (a0 + a1) + (a2 + a3);
    float c = g_c[slot * Nn + tid];
    float cn = (acc == 0.f) ? 0.f : c / fmaxf(c * acc, EPSV);
    g_c[slot * Nn + tid] = cn;
}

// ---------------------------------------------------------------------------
// NDCG final: approx_rel rows 0..9, top-10 by score, top-10 rel, DCG math.
// ---------------------------------------------------------------------------
__global__ void __launch_bounds__(512) ndcg_kernel(const float* __restrict__ s_ndcg,
                                                   const float* __restrict__ rel_g,
                                                   float* __restrict__ out) {
    int u = blockIdx.x;
    int slot = u;
    int tid = threadIdx.x;
    __shared__ float sh_c[Nn], sh_rel[Nn], sh_sc[Nn];
    __shared__ float sh_ar[TOPK];
    __shared__ float red_v[Nn];
    __shared__ int   red_i[Nn];
    __shared__ float relbym[TOPK], bestrel[TOPK];
    sh_c[tid]   = g_c[slot * Nn + tid];
    sh_rel[tid] = rel_g[(size_t)u * Nn + tid];
    sh_sc[tid]  = s_ndcg[(size_t)u * Nn + tid];
    __syncthreads();
    int w = tid >> 5, lane = tid & 31;
    if (w < TOPK) {
        const float* row = g_M0 + (size_t)slot * Nn * Nn + (size_t)w * Nn;
        float acc = 0.f;
#pragma unroll
        for (int k = 0; k < 16; k++) {
            int j = (k << 5) + lane;
            acc = fmaf(sh_c[j] * row[j], sh_rel[j], acc);
        }
#pragma unroll
        for (int o = 16; o > 0; o >>= 1) acc += __shfl_xor_sync(0xffffffffu, acc, o);
        if (lane == 0) sh_ar[w] = g_r[slot * Nn + w] * acc;
    }
    // --- top-10 by model score -> rel_by_model ---
    float myv = sh_sc[tid];
    for (int t = 0; t < TOPK; t++) {
        red_v[tid] = myv; red_i[tid] = tid;
        __syncthreads();
        for (int s = 256; s > 0; s >>= 1) {
            if (tid < s) {
                float b = red_v[tid + s]; int bi = red_i[tid + s];
                if (b > red_v[tid] || (b == red_v[tid] && bi < red_i[tid])) {
                    red_v[tid] = b; red_i[tid] = bi;
                }
            }
            __syncthreads();
        }
        int idx = red_i[0];
        if (tid == 0) relbym[t] = sh_rel[idx];
        __syncthreads();
        if (tid == idx) myv = -CUDART_INF_F;
    }
    // --- top-10 of relevance -> best ---
    float myr = sh_rel[tid];
    for (int t = 0; t < TOPK; t++) {
        red_v[tid] = myr; red_i[tid] = tid;
        __syncthreads();
        for (int s = 256; s > 0; s >>= 1) {
            if (tid < s) {
                float b = red_v[tid + s]; int bi = red_i[tid + s];
                if (b > red_v[tid] || (b == red_v[tid] && bi < red_i[tid])) {
                    red_v[tid] = b; red_i[tid] = bi;
                }
            }
            __syncthreads();
        }
        int idx = red_i[0];
        if (tid == 0) bestrel[t] = sh_rel[idx];
        __syncthreads();
        if (tid == idx) myr = -CUDART_INF_F;
    }
    if (tid == 0) {
        float da = 0.f, dm = 0.f, db = 0.f;
        for (int t = 0; t < TOPK; t++) {
            float disc = log2f((float)(t + 2));
            da += (exp2f(sh_ar[t])  - 1.f) / disc;
            dm += (exp2f(relbym[t]) - 1.f) / disc;
            db += (exp2f(bestrel[t]) - 1.f) / disc;
        }
        out[u]      = da / db;
        out[Uu + u] = dm / db;
    }
}

// ---------------------------------------------------------------------------
// Diversity final: approx_rank column reduction, sigmoid, rank-1 identities.
// ---------------------------------------------------------------------------
__global__ void __launch_bounds__(512) div_kernel(const float* __restrict__ batch,
                                                  const float* __restrict__ s_div,
                                                  float* __restrict__ out) {
    int u = blockIdx.x;
    int slot = Uu + u;
    int tid = threadIdx.x;
    __shared__ float sh_rw[Nn];
    __shared__ float sh_ar[Nn];
    __shared__ float sh_sc[Nn];
    __shared__ int   sh_mask[Nn];
    __shared__ float red_v[Nn];
    __shared__ int   red_i[Nn];
    __shared__ float gsh[FUF], hsh[FUF];
    __shared__ float sS1, sS2, sQ, sQh;
    sh_rw[tid]  = g_r[slot * Nn + tid] * (float)(Nn - tid);  // r_i * w_i, w_i = N-i
    sh_sc[tid]  = s_div[(size_t)u * Nn + tid];
    sh_mask[tid] = 0;
    if (tid < FUF) { gsh[tid] = 0.f; hsh[tid] = 0.f; }
    if (tid == 0) { sS1 = 0.f; sS2 = 0.f; sQ = 0.f; sQh = 0.f; }
    __syncthreads();
    // approx_rank_j = c_j * sum_i (r_i w_i) M0[i,j]; then sigmoid(ar - 502)
    {
        const float* cb = g_M0 + (size_t)slot * Nn * Nn + tid;
        float a0 = 0.f, a1 = 0.f, a2 = 0.f, a3 = 0.f;
#pragma unroll 4
        for (int i = 0; i < Nn; i += 4) {
            a0 = fmaf(sh_rw[i    ], cb[(size_t)(i    ) * Nn], a0);
            a1 = fmaf(sh_rw[i + 1], cb[(size_t)(i + 1) * Nn], a1);
            a2 = fmaf(sh_rw[i + 2], cb[(size_t)(i + 2) * Nn], a2);
            a3 = fmaf(sh_rw[i + 3], cb[(size_t)(i + 3) * Nn], a3);
        }
        float ar_raw = g_c[slot * Nn + tid] * ((a0 + a1) + (a2 + a3));
        sh_ar[tid] = 1.f / (1.f + expf((float)(Nn - TOPK) - ar_raw));
    }
    __syncthreads();
    // top-10 by div score -> binary mask (== clip(rank-502,0,1))
    float myv = sh_sc[tid];
    for (int t = 0; t < TOPK; t++) {
        red_v[tid] = myv; red_i[tid] = tid;
        __syncthreads();
        for (int s = 256; s > 0; s >>= 1) {
            if (tid < s) {
                float b = red_v[tid + s]; int bi = red_i[tid + s];
                if (b > red_v[tid] || (b == red_v[tid] && bi < red_i[tid])) {
                    red_v[tid] = b; red_i[tid] = bi;
                }
            }
            __syncthreads();
        }
        int idx = red_i[0];
        __syncthreads();
        if (tid == idx) { myv = -CUDART_INF_F; sh_mask[tid] = 1; }
    }
    __syncthreads();
    // items phase: warp per item, lane owns feats {2l, 2l+1}
    int w = tid >> 5, lane = tid & 31;
    float gx = 0.f, gy = 0.f, hx = 0.f, hy = 0.f;
    float s1 = 0.f, s2 = 0.f, q = 0.f, qh = 0.f;
    for (int ii = 0; ii < 32; ii++) {
        int j = (w << 5) + ii;
        const float2 xy = *(const float2*)(batch + ((size_t)(u * Nn + j)) * Ff + 2 * lane);
        float nr = xy.x * xy.x + xy.y * xy.y;
#pragma unroll
        for (int o = 16; o > 0; o >>= 1) nr += __shfl_xor_sync(0xffffffffu, nr, o);
        float nrm = sqrtf(nr);
        float inv = 1.f / fmaxf(nrm, 1e-8f);
        float nn = nr * inv * inv;     // ||n_j||^2 (== 1 unless norm clipped)
        float a = sh_ar[j];
        gx += a * xy.x * inv; gy += a * xy.y * inv;
        int m = sh_mask[j];
        if (m) { hx += xy.x * inv; hy += xy.y * inv; }
        if (lane == 0) {
            s1 += a; s2 += a * a; q += a * a * nn;
            if (m) qh += nn;
        }
    }
    atomicAdd(&gsh[2 * lane], gx); atomicAdd(&gsh[2 * lane + 1], gy);
    atomicAdd(&hsh[2 * lane], hx); atomicAdd(&hsh[2 * lane + 1], hy);
    if (lane == 0) {
        atomicAdd(&sS1, s1); atomicAdd(&sS2, s2);
        atomicAdd(&sQ, q);   atomicAdd(&sQh, qh);
    }
    __syncthreads();
    if (tid == 0) {
        float G2 = 0.f, H2 = 0.f;
        for (int f = 0; f < FUF; f++) { G2 += gsh[f] * gsh[f]; H2 += hsh[f] * hsh[f]; }
        float S1 = sS1, S2v = sS2;
        float denomA = S1 * S1 - S2v;                    // 2 * sum_{i<j} ar_i ar_j
        float approx_div = 1.f - (G2 - sQ) / denomA;
        float numR = 45.f - 0.5f * (H2 - sQh);           // sum_{i<j in T} dis
        out[2 * Uu + u] = approx_div;
        out[3 * Uu + u] = numR / 45.f;
    }
}

// ---------------------------------------------------------------------------
extern "C" void kernel_launch(void* const* d_in, const int* in_sizes, int n_in,
                              void* d_out, int out_size) {
    const float* batch  = (const float*)d_in[0];
    const float* s_div  = (const float*)d_in[1];
    const float* s_ndcg = (const float*)d_in[2];
    const float* rel    = (const float*)d_in[3];
    float* out = (float*)d_out;

    init_kernel<<<SLOTS, Nn>>>(s_ndcg, s_div);           // softmax + col pass #1
    for (int it = 0; it < 5; it++) {
        row_kernel<<<SLOTS, Nn>>>();                     // row passes #1..#5
        if (it < 4) col_kernel<<<SLOTS, Nn>>>();         // col passes #2..#5
    }
    ndcg_kernel<<<Uu, Nn>>>(s_ndcg, rel, out);
    div_kernel<<<Uu, Nn>>>(batch, s_div, out);
}

// round 2
// speedup vs baseline: 1.8921x; 1.8921x over previous
#include <cuda_runtime.h>
#include <math.h>
#include <math_constants.h>

#define Uu    128
#define Nn    512
#define Ff    80
#define FUF   64
#define TOPK  10
#define EPSV  1e-10f
#define C10L2E 14.4269504088896340736f   // 10 * log2(e)

__device__ __forceinline__ float warp_sum(float v) {
#pragma unroll
    for (int o = 16; o > 0; o >>= 1) v += __shfl_xor_sync(0xffffffffu, v, o);
    return v;
}
__device__ __forceinline__ float warp_max(float v) {
#pragma unroll
    for (int o = 16; o > 0; o >>= 1) v = fmaxf(v, __shfl_xor_sync(0xffffffffu, v, o));
    return v;
}

// warp-collective: repeated argmax (value desc, index asc) over vals[0..511].
// all lanes return the same idxs[t].
__device__ __forceinline__ void warp_top10_idx(const float* vals, int lane, int* idxs) {
    float mv[16];
#pragma unroll
    for (int k = 0; k < 16; k++) mv[k] = vals[(k << 5) + lane];
    for (int t = 0; t < TOPK; t++) {
        float bv = -CUDART_INF_F; int bi = Nn;
#pragma unroll
        for (int k = 0; k < 16; k++) {
            int j = (k << 5) + lane;
            if (mv[k] > bv || (mv[k] == bv && j < bi)) { bv = mv[k]; bi = j; }
        }
#pragma unroll
        for (int o = 16; o > 0; o >>= 1) {
            float ov = __shfl_xor_sync(0xffffffffu, bv, o);
            int   oi = __shfl_xor_sync(0xffffffffu, bi, o);
            if (ov > bv || (ov == bv && oi < bi)) { bv = ov; bi = oi; }
        }
        idxs[t] = bi;
        if ((bi & 31) == lane) mv[bi >> 5] = -CUDART_INF_F;
    }
}

__global__ void __launch_bounds__(512, 1) mega_kernel(
    const float* __restrict__ batch, const float* __restrict__ s_div,
    const float* __restrict__ s_ndcg, const float* __restrict__ rel_g,
    float* __restrict__ out)
{
    __shared__ float sh_s[Nn], sh_A[Nn], sh_mxl[Nn], sh_inv[Nn], sh_c[Nn], sh_r[Nn];
    __shared__ float sh_colw[8][Nn];
    __shared__ float sh_rel[Nn];
    __shared__ float sh_rank[Nn];
    __shared__ float sh_arel[TOPK], sh_t10v[TOPK], sh_t10b[TOPK];
    __shared__ int   sh_mask[Nn];
    __shared__ float sh_gp[16][FUF], sh_hp[16][FUF];
    __shared__ float sh_scal[16][4];
    __shared__ float sh_red[FUF];

    int slot = blockIdx.x;
    bool isdiv = slot >= Uu;
    int u = isdiv ? slot - Uu : slot;
    int tid = threadIdx.x, w = tid >> 5, lane = tid & 31;

    const float* sp = isdiv ? (s_div + (size_t)u * Nn) : (s_ndcg + (size_t)u * Nn);
    sh_s[tid] = sp[tid];
    if (!isdiv) sh_rel[tid] = rel_g[(size_t)u * Nn + tid];
    sh_r[tid] = 1.0f;
    sh_mask[tid] = 0;
    __syncthreads();

    // a_sum
    {
        float sj = sh_s[tid]; float a = 0.f;
        for (int k2 = 0; k2 < Nn; k2++) a += fabsf(sj - sh_s[k2]);
        sh_A[tid] = a;
    }
    __syncthreads();

    float Sj[16], Aj[16];
#pragma unroll
    for (int k = 0; k < 16; k++) { int j = (k << 5) + lane; Sj[k] = sh_s[j]; Aj[k] = sh_A[j]; }

    float colacc[16];

    // ---------------- scan 1: softmax stats + Sinkhorn col pass #1 (r = 1)
#pragma unroll
    for (int k = 0; k < 16; k++) colacc[k] = 0.f;
    for (int ii = 0; ii < 32; ii++) {
        int i = (w << 5) + ii;
        float v = (float)(Nn - 1 - 2 * i);
        float l[16]; float mx = -CUDART_INF_F;
#pragma unroll
        for (int k = 0; k < 16; k++) {
            float lv = __fsub_rn(__fmul_rn(v, Sj[k]), Aj[k]);
            l[k] = lv; mx = fmaxf(mx, lv);
        }
        mx = warp_max(mx);
        float thr = mx - 10.5f;          // == x >= mx*10 - 105 in logit space
        float nm  = -mx * C10L2E;
        float sum = 0.f;
#pragma unroll
        for (int k = 0; k < 16; k++) {
            float e = (l[k] >= thr) ? exp2f(fmaf(l[k], C10L2E, nm)) : 0.f;
            l[k] = e; sum += e;
        }
        sum = warp_sum(sum);
        float inv = 1.f / sum;           // sum >= 1 always (max entry -> 1)
        if (lane == 0) { sh_mxl[i] = mx; sh_inv[i] = inv; }
#pragma unroll
        for (int k = 0; k < 16; k++) colacc[k] = fmaf(inv, l[k], colacc[k]);
    }
#pragma unroll
    for (int k = 0; k < 16; k++) { if (w >= 8) sh_colw[w - 8][(k << 5) + lane] = colacc[k]; }
    __syncthreads();
#pragma unroll
    for (int k = 0; k < 16; k++) { if (w < 8) sh_colw[w][(k << 5) + lane] += colacc[k]; }
    __syncthreads();
    {
        float acc = 0.f;
#pragma unroll
        for (int b = 0; b < 8; b++) acc += sh_colw[b][tid];
        sh_c[tid] = (acc == 0.f) ? 0.f : (1.f / fmaxf(acc, EPSV));
    }
    __syncthreads();

    // ---------------- scans 2..5: fused row_k + col_{k+1}
    for (int itp = 0; itp < 4; itp++) {
        float cj[16];
#pragma unroll
        for (int k = 0; k < 16; k++) cj[k] = sh_c[(k << 5) + lane];
#pragma unroll
        for (int k = 0; k < 16; k++) colacc[k] = 0.f;
        for (int ii = 0; ii < 32; ii++) {
            int i = (w << 5) + ii;
            float v = (float)(Nn - 1 - 2 * i);
            float mx = sh_mxl[i], inv = sh_inv[i];
            float thr = mx - 10.5f, nm = -mx * C10L2E;
            float e[16]; float racc = 0.f;
#pragma unroll
            for (int k = 0; k < 16; k++) {
                float lv = __fsub_rn(__fmul_rn(v, Sj[k]), Aj[k]);
                float ev = (lv >= thr) ? exp2f(fmaf(lv, C10L2E, nm)) : 0.f;
                e[k] = ev;
                racc = fmaf(cj[k], ev, racc);
            }
            racc = warp_sum(racc);
            float rowsum = inv * racc;                 // sum_j c_j * p_ij
            float r = sh_r[i];
            float rn = (rowsum == 0.f) ? 0.f : (r / fmaxf(r * rowsum, EPSV));
            if (lane == 0) sh_r[i] = rn;
            float rho = rn * inv;
#pragma unroll
            for (int k = 0; k < 16; k++) colacc[k] = fmaf(rho, e[k], colacc[k]);
        }
#pragma unroll
        for (int k = 0; k < 16; k++) { if (w >= 8) sh_colw[w - 8][(k << 5) + lane] = colacc[k]; }
        __syncthreads();
#pragma unroll
        for (int k = 0; k < 16; k++) { if (w < 8) sh_colw[w][(k << 5) + lane] += colacc[k]; }
        __syncthreads();
        float acc = 0.f;
#pragma unroll
        for (int b = 0; b < 8; b++) acc += sh_colw[b][tid];
        float c = sh_c[tid];
        float cn = (acc == 0.f) ? 0.f : (c / fmaxf(c * acc, EPSV));
        __syncthreads();
        sh_c[tid] = cn;
        __syncthreads();
    }

    // ---------------- scan 6: final row pass + approx_rel (ndcg) / approx_rank (div)
    {
        float cj[16];
#pragma unroll
        for (int k = 0; k < 16; k++) cj[k] = sh_c[(k << 5) + lane];
#pragma unroll
        for (int k = 0; k < 16; k++) colacc[k] = 0.f;
        for (int ii = 0; ii < 32; ii++) {
            int i = (w << 5) + ii;
            float v = (float)(Nn - 1 - 2 * i);
            float mx = sh_mxl[i], inv = sh_inv[i];
            float thr = mx - 10.5f, nm = -mx * C10L2E;
            float e[16]; float racc = 0.f;
#pragma unroll
            for (int k = 0; k < 16; k++) {
                float lv = __fsub_rn(__fmul_rn(v, Sj[k]), Aj[k]);
                float ev = (lv >= thr) ? exp2f(fmaf(lv, C10L2E, nm)) : 0.f;
                e[k] = ev;
                racc = fmaf(cj[k], ev, racc);
            }
            racc = warp_sum(racc);
            float rowsum = inv * racc;
            float r = sh_r[i];
            float rn = (rowsum == 0.f) ? 0.f : (r / fmaxf(r * rowsum, EPSV));
            if (!isdiv && i < TOPK) {
                float ra = 0.f;
#pragma unroll
                for (int k = 0; k < 16; k++)
                    ra = fmaf(cj[k] * e[k], sh_rel[(k << 5) + lane], ra);
                ra = warp_sum(ra);
                if (lane == 0) sh_arel[i] = rn * inv * ra;
            }
            float rho = isdiv ? rn * inv * (float)(Nn - i) : rn * inv;
#pragma unroll
            for (int k = 0; k < 16; k++) colacc[k] = fmaf(rho, e[k], colacc[k]);
        }
#pragma unroll
        for (int k = 0; k < 16; k++) { if (w >= 8) sh_colw[w - 8][(k << 5) + lane] = colacc[k]; }
        __syncthreads();
#pragma unroll
        for (int k = 0; k < 16; k++) { if (w < 8) sh_colw[w][(k << 5) + lane] += colacc[k]; }
        __syncthreads();
        float acc = 0.f;
#pragma unroll
        for (int b = 0; b < 8; b++) acc += sh_colw[b][tid];
        if (isdiv) {
            float arr = sh_c[tid] * acc;              // approx_rank_j
            sh_rank[tid] = 1.f / (1.f + expf((float)(Nn - TOPK) - arr));
        }
        __syncthreads();
    }

    // ---------------- finals
    if (!isdiv) {
        if (w == 0) {
            int idxs[TOPK];
            warp_top10_idx(sh_s, lane, idxs);
            if (lane == 0) {
#pragma unroll
                for (int t = 0; t < TOPK; t++) sh_t10v[t] = sh_rel[idxs[t]];
            }
        } else if (w == 1) {
            int idxs[TOPK];
            warp_top10_idx(sh_rel, lane, idxs);
            if (lane == 0) {
#pragma unroll
                for (int t = 0; t < TOPK; t++) sh_t10b[t] = sh_rel[idxs[t]];
            }
        }
        __syncthreads();
        if (tid == 0) {
            float da = 0.f, dm = 0.f, db = 0.f;
            for (int t = 0; t < TOPK; t++) {
                float disc = log2f((float)(t + 2));
                da += (exp2f(sh_arel[t]) - 1.f) / disc;
                dm += (exp2f(sh_t10v[t]) - 1.f) / disc;
                db += (exp2f(sh_t10b[t]) - 1.f) / disc;
            }
            out[u]      = da / db;
            out[Uu + u] = dm / db;
        }
    } else {
        if (w == 0) {
            int idxs[TOPK];
            warp_top10_idx(sh_s, lane, idxs);
            if (lane == 0) {
#pragma unroll
                for (int t = 0; t < TOPK; t++) sh_mask[idxs[t]] = 1;
            }
        }
        __syncthreads();
        // item phase: warp per 32 items, lane owns features {2l, 2l+1}
        float gx = 0.f, gy = 0.f, hx = 0.f, hy = 0.f;
        float s1 = 0.f, s2 = 0.f, q = 0.f, qh = 0.f;
        for (int ii = 0; ii < 32; ii++) {
            int j = (w << 5) + ii;
            const float2 xy = *(const float2*)(batch + ((size_t)(u * Nn + j)) * Ff + 2 * lane);
            float nr = xy.x * xy.x + xy.y * xy.y;
            nr = warp_sum(nr);
            float nrm = sqrtf(nr);
            float inv = 1.f / fmaxf(nrm, 1e-8f);
            float nn = nr * inv * inv;                // ||n_j||^2
            float a = sh_rank[j];
            gx += a * xy.x * inv; gy += a * xy.y * inv;
            int m = sh_mask[j];
            if (m) { hx += xy.x * inv; hy += xy.y * inv; }
            if (lane == 0) {
                s1 += a; s2 += a * a; q += a * a * nn;
                if (m) qh += nn;
            }
        }
        sh_gp[w][2 * lane] = gx; sh_gp[w][2 * lane + 1] = gy;
        sh_hp[w][2 * lane] = hx; sh_hp[w][2 * lane + 1] = hy;
        if (lane == 0) {
            sh_scal[w][0] = s1; sh_scal[w][1] = s2;
            sh_scal[w][2] = q;  sh_scal[w][3] = qh;
        }
        __syncthreads();
        if (tid < FUF) {
            float gf = 0.f, hf = 0.f;
#pragma unroll
            for (int ww = 0; ww < 16; ww++) { gf += sh_gp[ww][tid]; hf += sh_hp[ww][tid]; }
            sh_red[tid] = gf * gf;
            sh_gp[0][tid] = hf * hf;
        }
        __syncthreads();
        if (tid == 0) {
            float G2 = 0.f, H2 = 0.f;
            for (int f = 0; f < FUF; f++) { G2 += sh_red[f]; H2 += sh_gp[0][f]; }
            float S1 = 0.f, S2v = 0.f, Q = 0.f, Qh = 0.f;
            for (int ww = 0; ww < 16; ww++) {
                S1 += sh_scal[ww][0]; S2v += sh_scal[ww][1];
                Q  += sh_scal[ww][2]; Qh  += sh_scal[ww][3];
            }
            float denomA = S1 * S1 - S2v;             // 2 * sum_{i<j} a_i a_j
            float approx_div = 1.f - (G2 - Q) / denomA;
            float numR = 45.f - 0.5f * (H2 - Qh);     // sum_{i<j in T10} dis
            out[2 * Uu + u] = approx_div;
            out[3 * Uu + u] = numR / 45.f;
        }
    }
}

// ---------------------------------------------------------------------------
extern "C" void kernel_launch(void* const* d_in, const int* in_sizes, int n_in,
                              void* d_out, int out_size) {
    const float* batch  = (const float*)d_in[0];
    const float* s_div  = (const float*)d_in[1];
    const float* s_ndcg = (const float*)d_in[2];
    const float* rel    = (const float*)d_in[3];
    float* out = (float*)d_out;

    mega_kernel<<<256, 512>>>(batch, s_div, s_ndcg, rel, out);
}

// round 3
// speedup vs baseline: 3.0868x; 1.6314x over previous
#include <cuda_runtime.h>
#include <math.h>
#include <math_constants.h>

#define Uu    128
#define Nn    512
#define Ff    80
#define FUF   64
#define TOPK  10
#define EPSV  1e-10f
#define C10L2E 14.4269504088896340736f   // 10 * log2(e)

__device__ __forceinline__ float ex2(float x) {
    float r;
    asm("ex2.approx.ftz.f32 %0, %1;" : "=f"(r) : "f"(x));
    return r;
}

__device__ __forceinline__ float warp_sum(float v) {
#pragma unroll
    for (int o = 16; o > 0; o >>= 1) v += __shfl_xor_sync(0xffffffffu, v, o);
    return v;
}
__device__ __forceinline__ float warp_max(float v) {
#pragma unroll
    for (int o = 16; o > 0; o >>= 1) v = fmaxf(v, __shfl_xor_sync(0xffffffffu, v, o));
    return v;
}

// warp-collective: repeated argmax (value desc, index asc) over vals[0..511].
__device__ __forceinline__ void warp_top10_idx(const float* vals, int lane, int* idxs) {
    float mv[16];
#pragma unroll
    for (int k = 0; k < 16; k++) mv[k] = vals[(k << 5) + lane];
    for (int t = 0; t < TOPK; t++) {
        float bv = -CUDART_INF_F; int bi = Nn;
#pragma unroll
        for (int k = 0; k < 16; k++) {
            int j = (k << 5) + lane;
            if (mv[k] > bv || (mv[k] == bv && j < bi)) { bv = mv[k]; bi = j; }
        }
#pragma unroll
        for (int o = 16; o > 0; o >>= 1) {
            float ov = __shfl_xor_sync(0xffffffffu, bv, o);
            int   oi = __shfl_xor_sync(0xffffffffu, bi, o);
            if (ov > bv || (ov == bv && oi < bi)) { bv = ov; bi = oi; }
        }
        idxs[t] = bi;
        if ((bi & 31) == lane) mv[bi >> 5] = -CUDART_INF_F;
    }
}

__global__ void __launch_bounds__(512, 1) mega_kernel(
    const float* __restrict__ batch, const float* __restrict__ s_div,
    const float* __restrict__ s_ndcg, const float* __restrict__ rel_g,
    float* __restrict__ out)
{
    __shared__ float sh_s[Nn], sh_A[Nn], sh_mxl[Nn], sh_inv[Nn], sh_c[Nn], sh_r[Nn];
    __shared__ float sh_colw[8][Nn];
    __shared__ float sh_rel[Nn];
    __shared__ float sh_rank[Nn];
    __shared__ float sh_arel[TOPK], sh_t10v[TOPK], sh_t10b[TOPK];
    __shared__ int   sh_mask[Nn];
    __shared__ float sh_gp[16][FUF], sh_hp[16][FUF];
    __shared__ float sh_scal[16][4];
    __shared__ float sh_red[FUF];

    int slot = blockIdx.x;
    bool isdiv = slot >= Uu;
    int u = isdiv ? slot - Uu : slot;
    int tid = threadIdx.x, w = tid >> 5, lane = tid & 31;

    const float* sp = isdiv ? (s_div + (size_t)u * Nn) : (s_ndcg + (size_t)u * Nn);
    sh_s[tid] = sp[tid];
    if (!isdiv) sh_rel[tid] = rel_g[(size_t)u * Nn + tid];
    sh_r[tid] = 1.0f;
    sh_mask[tid] = 0;
    __syncthreads();

    // a_sum
    {
        float sj = sh_s[tid]; float a = 0.f;
        for (int k2 = 0; k2 < Nn; k2++) a += fabsf(sj - sh_s[k2]);
        sh_A[tid] = a;
    }
    __syncthreads();

    float Sj[16], nAj[16];
#pragma unroll
    for (int k = 0; k < 16; k++) { int j = (k << 5) + lane; Sj[k] = sh_s[j]; nAj[k] = -sh_A[j]; }

    float colacc[16];

    // ---------------- scan 1: softmax stats + Sinkhorn col pass #1 (r = 1)
#pragma unroll
    for (int k = 0; k < 16; k++) colacc[k] = 0.f;
    for (int ii = 0; ii < 32; ii++) {
        int i = (w << 5) + ii;
        float v = (float)(Nn - 1 - 2 * i);
        float l[16]; float mx = -CUDART_INF_F;
#pragma unroll
        for (int k = 0; k < 16; k++) {
            float lv = fmaf(v, Sj[k], nAj[k]);
            l[k] = lv; mx = fmaxf(mx, lv);
        }
        mx = warp_max(mx);
        float nm = -mx * C10L2E;
        float sum = 0.f;
#pragma unroll
        for (int k = 0; k < 16; k++) {
            float e = ex2(fmaf(l[k], C10L2E, nm));
            l[k] = e; sum += e;
        }
        sum = warp_sum(sum);
        float inv = 1.f / sum;           // sum >= 1 always (max entry -> 1)
        if (lane == 0) { sh_mxl[i] = mx; sh_inv[i] = inv; }
#pragma unroll
        for (int k = 0; k < 16; k++) colacc[k] = fmaf(inv, l[k], colacc[k]);
    }
#pragma unroll
    for (int k = 0; k < 16; k++) { if (w >= 8) sh_colw[w - 8][(k << 5) + lane] = colacc[k]; }
    __syncthreads();
#pragma unroll
    for (int k = 0; k < 16; k++) { if (w < 8) sh_colw[w][(k << 5) + lane] += colacc[k]; }
    __syncthreads();
    {
        float acc = 0.f;
#pragma unroll
        for (int b = 0; b < 8; b++) acc += sh_colw[b][tid];
        sh_c[tid] = (acc == 0.f) ? 0.f : (1.f / fmaxf(acc, EPSV));
    }
    __syncthreads();

    // ---------------- scans 2..5: fused row_k + col_{k+1}
    for (int itp = 0; itp < 4; itp++) {
        float cj[16];
#pragma unroll
        for (int k = 0; k < 16; k++) cj[k] = sh_c[(k << 5) + lane];
#pragma unroll
        for (int k = 0; k < 16; k++) colacc[k] = 0.f;
        for (int ii = 0; ii < 32; ii++) {
            int i = (w << 5) + ii;
            float v = (float)(Nn - 1 - 2 * i);
            float nm = -sh_mxl[i] * C10L2E, inv = sh_inv[i];
            float e[16]; float racc = 0.f;
#pragma unroll
            for (int k = 0; k < 16; k++) {
                float lv = fmaf(v, Sj[k], nAj[k]);
                float ev = ex2(fmaf(lv, C10L2E, nm));
                e[k] = ev;
                racc = fmaf(cj[k], ev, racc);
            }
            racc = warp_sum(racc);
            float rowsum = inv * racc;                 // sum_j c_j * p_ij
            float r = sh_r[i];
            float rn = (rowsum == 0.f) ? 0.f : (r / fmaxf(r * rowsum, EPSV));
            if (lane == 0) sh_r[i] = rn;
            float rho = rn * inv;
#pragma unroll
            for (int k = 0; k < 16; k++) colacc[k] = fmaf(rho, e[k], colacc[k]);
        }
#pragma unroll
        for (int k = 0; k < 16; k++) { if (w >= 8) sh_colw[w - 8][(k << 5) + lane] = colacc[k]; }
        __syncthreads();
#pragma unroll
        for (int k = 0; k < 16; k++) { if (w < 8) sh_colw[w][(k << 5) + lane] += colacc[k]; }
        __syncthreads();
        float acc = 0.f;
#pragma unroll
        for (int b = 0; b < 8; b++) acc += sh_colw[b][tid];
        float c = sh_c[tid];
        float cn = (acc == 0.f) ? 0.f : (c / fmaxf(c * acc, EPSV));
        __syncthreads();
        sh_c[tid] = cn;
        __syncthreads();
    }

    // ---------------- scan 6: final row pass + approx_rel (ndcg) / approx_rank (div)
    {
        float cj[16];
#pragma unroll
        for (int k = 0; k < 16; k++) cj[k] = sh_c[(k << 5) + lane];
#pragma unroll
        for (int k = 0; k < 16; k++) colacc[k] = 0.f;
        for (int ii = 0; ii < 32; ii++) {
            int i = (w << 5) + ii;
            float v = (float)(Nn - 1 - 2 * i);
            float nm = -sh_mxl[i] * C10L2E, inv = sh_inv[i];
            float e[16]; float racc = 0.f;
#pragma unroll
            for (int k = 0; k < 16; k++) {
                float lv = fmaf(v, Sj[k], nAj[k]);
                float ev = ex2(fmaf(lv, C10L2E, nm));
                e[k] = ev;
                racc = fmaf(cj[k], ev, racc);
            }
            racc = warp_sum(racc);
            float rowsum = inv * racc;
            float r = sh_r[i];
            float rn = (rowsum == 0.f) ? 0.f : (r / fmaxf(r * rowsum, EPSV));
            if (!isdiv && i < TOPK) {
                float ra = 0.f;
#pragma unroll
                for (int k = 0; k < 16; k++)
                    ra = fmaf(cj[k] * e[k], sh_rel[(k << 5) + lane], ra);
                ra = warp_sum(ra);
                if (lane == 0) sh_arel[i] = rn * inv * ra;
            }
            float rho = isdiv ? rn * inv * (float)(Nn - i) : rn * inv;
#pragma unroll
            for (int k = 0; k < 16; k++) colacc[k] = fmaf(rho, e[k], colacc[k]);
        }
#pragma unroll
        for (int k = 0; k < 16; k++) { if (w >= 8) sh_colw[w - 8][(k << 5) + lane] = colacc[k]; }
        __syncthreads();
#pragma unroll
        for (int k = 0; k < 16; k++) { if (w < 8) sh_colw[w][(k << 5) + lane] += colacc[k]; }
        __syncthreads();
        float acc = 0.f;
#pragma unroll
        for (int b = 0; b < 8; b++) acc += sh_colw[b][tid];
        if (isdiv) {
            float arr = sh_c[tid] * acc;              // approx_rank_j
            sh_rank[tid] = 1.f / (1.f + expf((float)(Nn - TOPK) - arr));
        }
        __syncthreads();
    }

    // ---------------- finals
    if (!isdiv) {
        if (w == 0) {
            int idxs[TOPK];
            warp_top10_idx(sh_s, lane, idxs);
            if (lane == 0) {
#pragma unroll
                for (int t = 0; t < TOPK; t++) sh_t10v[t] = sh_rel[idxs[t]];
            }
        } else if (w == 1) {
            int idxs[TOPK];
            warp_top10_idx(sh_rel, lane, idxs);
            if (lane == 0) {
#pragma unroll
                for (int t = 0; t < TOPK; t++) sh_t10b[t] = sh_rel[idxs[t]];
            }
        }
        __syncthreads();
        if (tid == 0) {
            float da = 0.f, dm = 0.f, db = 0.f;
            for (int t = 0; t < TOPK; t++) {
                float disc = log2f((float)(t + 2));
                da += (exp2f(sh_arel[t]) - 1.f) / disc;
                dm += (exp2f(sh_t10v[t]) - 1.f) / disc;
                db += (exp2f(sh_t10b[t]) - 1.f) / disc;
            }
            out[u]      = da / db;
            out[Uu + u] = dm / db;
        }
    } else {
        if (w == 0) {
            int idxs[TOPK];
            warp_top10_idx(sh_s, lane, idxs);
            if (lane == 0) {
#pragma unroll
                for (int t = 0; t < TOPK; t++) sh_mask[idxs[t]] = 1;
            }
        }
        __syncthreads();
        // item phase: warp per 32 items, lane owns features {2l, 2l+1}
        float gx = 0.f, gy = 0.f, hx = 0.f, hy = 0.f;
        float s1 = 0.f, s2 = 0.f, q = 0.f, qh = 0.f;
        for (int ii = 0; ii < 32; ii++) {
            int j = (w << 5) + ii;
            const float2 xy = *(const float2*)(batch + ((size_t)(u * Nn + j)) * Ff + 2 * lane);
            float nr = xy.x * xy.x + xy.y * xy.y;
            nr = warp_sum(nr);
            float nrm = sqrtf(nr);
            float inv = 1.f / fmaxf(nrm, 1e-8f);
            float nn = nr * inv * inv;                // ||n_j||^2
            float a = sh_rank[j];
            gx += a * xy.x * inv; gy += a * xy.y * inv;
            int m = sh_mask[j];
            if (m) { hx += xy.x * inv; hy += xy.y * inv; }
            if (lane == 0) {
                s1 += a; s2 += a * a; q += a * a * nn;
                if (m) qh += nn;
            }
        }
        sh_gp[w][2 * lane] = gx; sh_gp[w][2 * lane + 1] = gy;
        sh_hp[w][2 * lane] = hx; sh_hp[w][2 * lane + 1] = hy;
        if (lane == 0) {
            sh_scal[w][0] = s1; sh_scal[w][1] = s2;
            sh_scal[w][2] = q;  sh_scal[w][3] = qh;
        }
        __syncthreads();
        if (tid < FUF) {
            float gf = 0.f, hf = 0.f;
#pragma unroll
            for (int ww = 0; ww < 16; ww++) { gf += sh_gp[ww][tid]; hf += sh_hp[ww][tid]; }
            sh_red[tid] = gf * gf;
            sh_gp[0][tid] = hf * hf;
        }
        __syncthreads();
        if (tid == 0) {
            float G2 = 0.f, H2 = 0.f;
            for (int f = 0; f < FUF; f++) { G2 += sh_red[f]; H2 += sh_gp[0][f]; }
            float S1 = 0.f, S2v = 0.f, Q = 0.f, Qh = 0.f;
            for (int ww = 0; ww < 16; ww++) {
                S1 += sh_scal[ww][0]; S2v += sh_scal[ww][1];
                Q  += sh_scal[ww][2]; Qh  += sh_scal[ww][3];
            }
            float denomA = S1 * S1 - S2v;             // 2 * sum_{i<j} a_i a_j
            float approx_div = 1.f - (G2 - Q) / denomA;
            float numR = 45.f - 0.5f * (H2 - Qh);     // sum_{i<j in T10} dis
            out[2 * Uu + u] = approx_div;
            out[3 * Uu + u] = numR / 45.f;
        }
    }
}

// ---------------------------------------------------------------------------
extern "C" void kernel_launch(void* const* d_in, const int* in_sizes, int n_in,
                              void* d_out, int out_size) {
    const float* batch  = (const float*)d_in[0];
    const float* s_div  = (const float*)d_in[1];
    const float* s_ndcg = (const float*)d_in[2];
    const float* rel    = (const float*)d_in[3];
    float* out = (float*)d_out;

    mega_kernel<<<256, 512>>>(batch, s_div, s_ndcg, rel, out);
}